// round 16
// baseline (speedup 1.0000x reference)
#include <cuda_runtime.h>

#define TLEN   2048
#define CSTEP  8
#define NCHUNK (TLEN / CSTEP)      // 256
#define XSTRIDE 68                 // floats per seq chunk block: 8*8 + 4 pad
#define SEQB   32                  // sequences per block

typedef unsigned long long u64;

// Fast HW tanh (MUFU.TANH).
__device__ __forceinline__ float ftanh_fast(float x) {
    float y;
    asm("tanh.approx.f32 %0, %1;" : "=f"(y) : "f"(x));
    return y;
}
// Exact-ish tanh for phase 2.
__device__ __forceinline__ float ftanh_exact(float x) {
    float e = __expf(2.f * x);
    return fmaf(-2.f, __frcp_rn(e + 1.f), 1.f);
}

// ---- packed f32x2 helpers -------------------------------------------------
__device__ __forceinline__ u64 pk2(float lo, float hi) {
    u64 r; asm("mov.b64 %0, {%1, %2};" : "=l"(r) : "f"(lo), "f"(hi)); return r;
}
__device__ __forceinline__ u64 fma2(u64 a, u64 b, u64 c) {
    u64 d; asm("fma.rn.f32x2 %0, %1, %2, %3;" : "=l"(d) : "l"(a), "l"(b), "l"(c));
    return d;
}
__device__ __forceinline__ float hadd2(u64 v) {
    float lo, hi; asm("mov.b64 {%0, %1}, %2;" : "=f"(lo), "=f"(hi) : "l"(v));
    return lo + hi;
}

// ---------------------------------------------------------------------------
// Fused kernel, 128 threads/block (4 warps), 128 blocks (1 warp/SMSP).
// Phase 1: warps 0-1 forward (seqs 0-15 / 16-31), warps 2-3 backward.
//   16 seqs per warp; lane = g*16 + r; group g=0 owns units 0..4,
//   g=1 owns units 5..8 (+ zero pad). One xor-16 shfl exchange per step.
//   Per lane: 5 independent 8-FFMA2 ladders -> high ILP inside the chain.
//   x staged via smem in 8-step chunks, one-chunk-ahead register prefetch
//   (st[5] -> low register pressure vs the 16-step variant).
// Phase 2: 25-step H2=32 RNN + projection, 4 warps x 8 seqs.
// ---------------------------------------------------------------------------
__global__ __launch_bounds__(128) void birnn_kernel(
    const float* __restrict__ x,
    const float* __restrict__ wih_f, const float* __restrict__ whh_f,
    const float* __restrict__ bih_f, const float* __restrict__ bhh_f,
    const float* __restrict__ wih_b, const float* __restrict__ whh_b,
    const float* __restrict__ bih_b, const float* __restrict__ bhh_b,
    const float* __restrict__ wih2, const float* __restrict__ whh2,
    const float* __restrict__ bih2, const float* __restrict__ bhh2,
    const float* __restrict__ wout, const float* __restrict__ bout,
    float* __restrict__ out)
{
    __shared__ __align__(16) float xs[2 * SEQB * XSTRIDE];   // 17,408 B
    __shared__ float ys[SEQB * 19];

    const int tid  = threadIdx.x;
    const int warp = tid >> 5;          // 0..3
    const int lane = tid & 31;
    const int isB  = warp >> 1;         // 0 fwd, 1 bwd
    const int g    = lane >> 4;         // unit-group 0..1
    const int r    = lane & 15;         // seq slot within warp
    const int s_loc = (warp & 1) * 16 + r;   // block-local seq 0..31

    const float* Wih = isB ? wih_b : wih_f;
    const float* Whh = isB ? whh_b : whh_f;
    const float* Bi  = isB ? bih_b : bih_f;
    const float* Bh  = isB ? bhh_b : bhh_f;

    // ---- weights: permute Whh cols to (own group, other group), pack f32x2
    // ladder pairs: P0=(x0,x1) P1=(x2,x3) P2=(x4,m0) P3=(m1,m2) P4=(m3,m4)
    //               P5=(o0,o1) P6=(o2,o3) P7=(o4, 0)
    u64 Wp[5][8];
    u64 bp[5];
#pragma unroll
    for (int k = 0; k < 5; k++) {
        const int u = g * 5 + k;            // my unit (u=9 is pad)
        const bool uv = (u < 9);
        float wi_[5], wo_[5], wn_[5];
#pragma unroll
        for (int j = 0; j < 5; j++)
            wi_[j] = uv ? Wih[u * 5 + j] : 0.f;
#pragma unroll
        for (int c = 0; c < 5; c++) {
            const int oc = g * 5 + c;           // own-group column
            const int xc = (1 - g) * 5 + c;     // other-group column
            wn_[c] = (uv && oc < 9) ? Whh[u * 9 + oc] : 0.f;
            wo_[c] = (uv && xc < 9) ? Whh[u * 9 + xc] : 0.f;
        }
        const float bias = uv ? (Bi[u] + Bh[u]) : 0.f;
        Wp[k][0] = pk2(wi_[0], wi_[1]);
        Wp[k][1] = pk2(wi_[2], wi_[3]);
        Wp[k][2] = pk2(wi_[4], wn_[0]);
        Wp[k][3] = pk2(wn_[1], wn_[2]);
        Wp[k][4] = pk2(wn_[3], wn_[4]);
        Wp[k][5] = pk2(wo_[0], wo_[1]);
        Wp[k][6] = pk2(wo_[2], wo_[3]);
        Wp[k][7] = pk2(wo_[4], 0.f);
        bp[k] = pk2(bias, 0.f);
    }

    float m0 = 0.f, m1 = 0.f, m2 = 0.f, m3 = 0.f, m4 = 0.f;  // own units
    float o0 = 0.f, o1 = 0.f, o2 = 0.f, o3 = 0.f, o4 = 0.f;  // other group

    // -------- staged x prefetch: 640 float4 per 8-step chunk-pair -----------
    // per seq per chunk: 8 steps x 5 floats = 40 floats = 10 float4.
    // fwd buffer (buf=0): chunk c = steps 8c..8c+7     (f4 base 10c)
    // bwd buffer (buf=1): chunk c = steps 2040-8c..2047-8c (f4 base 2550-10c)
    float4 st[5];
    auto loadStage = [&](int cn) {
        const int valid = (cn < NCHUNK);
        const int t4f = valid ? 10 * cn : 0;
        const int t4b = valid ? (2550 - 10 * cn) : 2550;
#pragma unroll
        for (int it = 0; it < 5; it++) {
            const int idx = tid + it * 128;             // 0..639
            const int buf = (idx >= 320);
            const int rem = idx - buf * 320;
            const int s   = rem / 10;
            const int k   = rem - s * 10;
            const int bg  = blockIdx.x * SEQB + s;
            const int f4i = bg * 2560 + (buf ? t4b : t4f) + k;
            st[it] = __ldg((const float4*)x + f4i);
        }
    };
    auto storeStage = [&]() {
#pragma unroll
        for (int it = 0; it < 5; it++) {
            const int idx = tid + it * 128;
            const int buf = (idx >= 320);
            const int rem = idx - buf * 320;
            const int s   = rem / 10;
            const int k   = rem - s * 10;
            float v[4] = { st[it].x, st[it].y, st[it].z, st[it].w };
#pragma unroll
            for (int jj = 0; jj < 4; jj++) {
                const int f = 4 * k + jj;               // 0..39
                const int trow = f / 5;                 // local time 0..7
                const int j = f - 5 * trow;
                xs[buf * (SEQB * XSTRIDE) + s * XSTRIDE + trow * 8 + j] = v[jj];
            }
        }
    };

    // backward warps walk rows 7 -> 0 (the ONLY time reversal)
    const float* xp0 = xs + isB * (SEQB * XSTRIDE) + s_loc * XSTRIDE + (isB ? 56 : 0);
    const int dstep = isB ? -8 : 8;

    loadStage(0);
    for (int c = 0; c < NCHUNK; c++) {
        storeStage();
        __syncthreads();
        loadStage(c + 1);           // hidden under the 8-step compute below

        const float* p = xp0;
#pragma unroll
        for (int i = 0; i < CSTEP; i++) {
            const float4 xv = *(const float4*)p;
            const float  x4 = p[4];
            p += dstep;

            u64 P[8];
            P[0] = pk2(xv.x, xv.y);
            P[1] = pk2(xv.z, xv.w);
            P[2] = pk2(x4, m0);
            P[3] = pk2(m1, m2);
            P[4] = pk2(m3, m4);
            P[5] = pk2(o0, o1);
            P[6] = pk2(o2, o3);
            P[7] = pk2(o4, 0.f);

            u64 a[5];
#pragma unroll
            for (int k = 0; k < 5; k++) a[k] = fma2(P[0], Wp[k][0], bp[k]);
#pragma unroll
            for (int q = 1; q < 8; q++) {
#pragma unroll
                for (int k = 0; k < 5; k++) a[k] = fma2(P[q], Wp[k][q], a[k]);
            }
            const float n0 = ftanh_fast(hadd2(a[0]));
            const float n1 = ftanh_fast(hadd2(a[1]));
            const float n2 = ftanh_fast(hadd2(a[2]));
            const float n3 = ftanh_fast(hadd2(a[3]));
            const float n4 = ftanh_fast(hadd2(a[4]));

            m0 = n0; m1 = n1; m2 = n2; m3 = n3; m4 = n4;
            o0 = __shfl_xor_sync(0xffffffffu, n0, 16);
            o1 = __shfl_xor_sync(0xffffffffu, n1, 16);
            o2 = __shfl_xor_sync(0xffffffffu, n2, 16);
            o3 = __shfl_xor_sync(0xffffffffu, n3, 16);
            o4 = __shfl_xor_sync(0xffffffffu, n4, 16);
        }
        __syncthreads();
    }

    // final hidden -> ys[s][dir*9 + u]
    {
        float mv[5] = { m0, m1, m2, m3, m4 };
#pragma unroll
        for (int k = 0; k < 5; k++) {
            const int u = g * 5 + k;
            if (u < 9) ys[s_loc * 19 + isB * 9 + u] = mv[k];
        }
    }
    __syncthreads();

    // ---------------- Phase 2: each warp handles 8 batch elements ----------
    float wh[32];
    {
        const float4* pw = (const float4*)(whh2 + lane * 32);
#pragma unroll
        for (int q = 0; q < 8; q++) {
            float4 v = pw[q];
            wh[q * 4 + 0] = v.x; wh[q * 4 + 1] = v.y;
            wh[q * 4 + 2] = v.z; wh[q * 4 + 3] = v.w;
        }
    }
    float wi[18];
#pragma unroll
    for (int j = 0; j < 18; j++) wi[j] = wih2[lane * 18 + j];
    const float bias2 = bih2[lane] + bhh2[lane];
    const float bo0 = bout[0], bo1 = bout[1], bo2 = bout[2];

    float* hsbuf = xs + warp * 825;     // reuse xs: 4 warps x 25*33 floats = 3300 < 4352

    for (int q = 0; q < 8; q++) {
        const int bl = warp * 8 + q;
        const long bg = (long)blockIdx.x * SEQB + bl;

        const float yv = (lane < 18) ? ys[bl * 19 + lane] : 0.f;
        float pre = bias2;
#pragma unroll
        for (int j = 0; j < 18; j++)
            pre = fmaf(__shfl_sync(0xffffffffu, yv, j), wi[j], pre);
        float h = ftanh_exact(pre);
        hsbuf[0 * 33 + lane] = h;

#pragma unroll 4
        for (int t = 1; t < 25; t++) {
            float pacc = bias2;
#pragma unroll
            for (int j = 0; j < 32; j++)
                pacc = fmaf(__shfl_sync(0xffffffffu, h, j), wh[j], pacc);
            h = ftanh_exact(pacc);
            hsbuf[t * 33 + lane] = h;
        }
        __syncwarp();

        if (lane < 25) {
            float a0 = bo0, a1 = bo1, a2 = bo2;
            const float* hrow = hsbuf + lane * 33;
#pragma unroll
            for (int j = 0; j < 32; j++) {
                const float hvv = hrow[j];
                a0 = fmaf(hvv, wout[j],      a0);
                a1 = fmaf(hvv, wout[32 + j], a1);
                a2 = fmaf(hvv, wout[64 + j], a2);
            }
            float* ob = out + bg * 75 + lane * 3;
            ob[0] = a0; ob[1] = a1; ob[2] = a2;
        }
        __syncwarp();
    }
}

extern "C" void kernel_launch(void* const* d_in, const int* in_sizes, int n_in,
                              void* d_out, int out_size)
{
    const float* x      = (const float*)d_in[0];
    const float* wih_f  = (const float*)d_in[1];
    const float* whh_f  = (const float*)d_in[2];
    const float* bih_f  = (const float*)d_in[3];
    const float* bhh_f  = (const float*)d_in[4];
    const float* wih_b  = (const float*)d_in[5];
    const float* whh_b  = (const float*)d_in[6];
    const float* bih_b  = (const float*)d_in[7];
    const float* bhh_b  = (const float*)d_in[8];
    const float* wih2   = (const float*)d_in[9];
    const float* whh2   = (const float*)d_in[10];
    const float* bih2   = (const float*)d_in[11];
    const float* bhh2   = (const float*)d_in[12];
    const float* wout   = (const float*)d_in[13];
    const float* bout   = (const float*)d_in[14];
    float* out = (float*)d_out;

    const int B = in_sizes[0] / (TLEN * 5);      // 4096
    birnn_kernel<<<B / SEQB, 128>>>(x,
        wih_f, whh_f, bih_f, bhh_f,
        wih_b, whh_b, bih_b, bhh_b,
        wih2, whh2, bih2, bhh2, wout, bout, out);
}